// round 10
// baseline (speedup 1.0000x reference)
#include <cuda_runtime.h>
#include <cuda_fp16.h>

typedef unsigned int u32;

namespace {
constexpr int B_ = 32, N_ = 25, H_ = 512, C_ = 1000;
constexpr int NP      = N_ * N_;   // 625
constexpr int M_ROWS  = B_ * N_;   // 800

// fp16 fragment-image geometry (u32 words)
constexpr int SUB_A   = 132;                   // 16m x 16k subtile (128 + pad)
constexpr int ATILE   = 16 * SUB_A;            // 2112 u32 per 128m x 32k chunk
constexpr int B_KT2   = 32 * 36;               // 1152
constexpr int BTILE   = 2 * B_KT2;             // 2304 u32 per 128n x 32k chunk

constexpr int SMEM_AB4  = 4 * (ATILE + BTILE) * 4;         // 70656 B
}

// ---------------- scratch (allocation-free device globals) ----------------
__device__ u32   g_Uh[M_ROWS * 256];
__device__ u32   g_Vh[M_ROWS * 256];
__device__ u32   g_Himg[(size_t)160 * 16 * ATILE];
__device__ u32   g_W1img[2 * 64 * BTILE];
__device__ u32   g_W2img[64 * BTILE];
__device__ u32   g_W3img[64 * BTILE];
__device__ float g_PART[160 * H_];
__device__ float g_Z1 [B_ * H_];
__device__ float g_Z2 [B_ * H_];
__device__ int   g_flags[192];   // 0:uv 1:h3 2:z1 3:z2, 8+by: h2_done[by]

// ---------------- helpers ----------------
__device__ __forceinline__ u32 h2pack(float lo, float hi) {
    __half2 h = __floats2half2_rn(lo, hi);
    return *(u32*)&h;
}
__device__ __forceinline__ u32 smem_u32(const void* p) {
    u32 a;
    asm("{ .reg .u64 t; cvta.to.shared.u64 t, %1; cvt.u32.u64 %0, t; }"
        : "=r"(a) : "l"(p));
    return a;
}
__device__ __forceinline__ void cpasync16(u32 saddr, const void* g) {
    asm volatile("cp.async.ca.shared.global [%0], [%1], 16;"
                 :: "r"(saddr), "l"(g) : "memory");
}
__device__ __forceinline__ void cp_commit() {
    asm volatile("cp.async.commit_group;" ::: "memory");
}
template<int NWAIT>
__device__ __forceinline__ void cp_wait() {
    asm volatile("cp.async.wait_group %0;" :: "n"(NWAIT) : "memory");
}
__device__ __forceinline__ void mma16(float* d, const u32* a, const u32* b) {
    asm volatile(
        "mma.sync.aligned.m16n8k16.row.col.f32.f16.f16.f32 "
        "{%0,%1,%2,%3}, {%4,%5,%6,%7}, {%8,%9}, {%0,%1,%2,%3};\n"
        : "+f"(d[0]), "+f"(d[1]), "+f"(d[2]), "+f"(d[3])
        : "r"(a[0]), "r"(a[1]), "r"(a[2]), "r"(a[3]), "r"(b[0]), "r"(b[1]));
}

// ---- flag sync (forward-only deps; producers have lower bids) ----
__device__ __forceinline__ void wait_flag(int idx, int target) {
    if (threadIdx.x == 0) {
        volatile int* f = &g_flags[idx];
        while (*f < target) __nanosleep(64);
    }
    __syncthreads();
    __threadfence();
}
__device__ __forceinline__ void bump_flag(int idx) {
    __threadfence();
    __syncthreads();
    if (threadIdx.x == 0) atomicAdd(&g_flags[idx], 1);
}

// ======================================================================
// weight repack (also resets flags for the fused kernel)
// ======================================================================
__global__ void repack_w(const float* __restrict__ w1a, const float* __restrict__ w1b,
                         const float* __restrict__ w2,  const float* __restrict__ w3)
{
    if (blockIdx.x == 0 && threadIdx.x < 192) g_flags[threadIdx.x] = 0;

    const u32 idx = blockIdx.x * 256 + threadIdx.x;   // 4 * 131072
    const int sel = idx >> 17;
    const int e   = idx & 131071;
    const int k2  = e >> 9;
    const int n   = e & 511;
    const int k0  = k2 * 2;
    const float* src = (sel == 0) ? w1a : (sel == 1) ? w1b : (sel == 2) ? w2 : w3;
    u32* dst = (sel == 0) ? g_W1img
             : (sel == 1) ? g_W1img + 64 * BTILE
             : (sel == 2) ? g_W2img : g_W3img;
    const float v0 = src[(size_t)k0 * 512 + n];
    const float v1 = src[(size_t)(k0 + 1) * 512 + n];
    const int nt  = n >> 7, nn = n & 127;
    const int kt  = k0 >> 5, kt2 = (k0 >> 4) & 1, kk = k0 & 15;
    const int lane = (nn & 7) * 4 + ((kk & 7) >> 1);
    const int j16  = nn >> 3;
    const int word = kt2 * B_KT2 + lane * 36 + (j16 >> 3) * 16 + (j16 & 7) * 2 + (kk >> 3);
    dst[(size_t)(nt * 16 + kt) * BTILE + word] = h2pack(v0, v1);
}

// ======================================================================
// fp16 tensor-core GEMM body (identical math to R9 kernel)
// ======================================================================
template<int AMODE, int EPI, int RT>
__device__ __forceinline__
void gemm_body(int bx, int by, const float* __restrict__ A,
               const u32* __restrict__ Bimg, const float* __restrict__ bias,
               float* __restrict__ C, float* __restrict__ C2, int M, u32* smem)
{
    const u32 sbase = smem_u32(smem);

    const int tid  = threadIdx.x;
    const int lane = tid & 31;
    const int wid  = tid >> 5;
    const int wm   = wid >> 1;
    const int wn   = wid & 1;

    const u32* bimg = Bimg;
    float*     Cdst = C;
    const float* beff = bias;
    int nt = bx;
    if (AMODE == 2) {
        if (bx >= 4) { bimg = Bimg + 64 * BTILE; Cdst = C2; beff = nullptr; }
        nt = bx & 3;
    }
    const int n0e = nt * 128;

    const int row_base = RT ? (by / 5) * NP + (by % 5) * 125 : by * 128;
    const int row_cap  = RT ? 125 : (M - row_base);

    const int lr8 = tid >> 3;
    const int kq  = tid & 7;
    const u32*   pu16[4];
    const u32*   pv16[4];
    const float* pa32[4];
    if (AMODE == 1 || AMODE == 2) {
        #pragma unroll
        for (int q = 0; q < 4; q++) {
            const int ml = lr8 + 32 * q;
            int m = row_base + ((ml < row_cap) ? ml : 0);
            if (AMODE == 1) {
                int b = m / NP; int r = m - b * NP;
                int i = r / N_; int j = r - i * N_;
                pu16[q] = g_Uh + (b * N_ + i) * 256;
                pv16[q] = g_Vh + (b * N_ + j) * 256;
            } else {
                pa32[q] = A + (size_t)m * 512;
            }
        }
    }

    uint2  sua[4], sva[4];
    float4 sau[4];

    auto bbuf = [&](int kt) -> u32* {
        if (AMODE == 3) return smem + (kt & 3) * (ATILE + BTILE) + ATILE;
        return smem + (kt & 3) * BTILE;
    };
    auto abuf = [&](int kt) -> u32* {
        if (AMODE == 3) return smem + (kt & 3) * (ATILE + BTILE);
        return smem + 4 * BTILE + (kt & 1) * ATILE;
    };

    auto cp_issue = [&](int kt) {
        if (kt < 16) {
            const u32 sB = sbase + (u32)((bbuf(kt) - smem) * 4);
            const u32* bsrc = bimg + (size_t)(nt * 16 + kt) * BTILE;
            for (int t = tid; t < BTILE / 4; t += 256)
                cpasync16(sB + t * 16, bsrc + t * 4);
            if (AMODE == 3) {
                const u32 sA = sbase + (u32)((abuf(kt) - smem) * 4);
                const u32* asrc = g_Himg + ((size_t)by * 16 + kt) * ATILE;
                for (int t = tid; t < ATILE / 4; t += 256)
                    cpasync16(sA + t * 16, asrc + t * 4);
            }
        }
        cp_commit();
    };

    auto ldg_a = [&](int kt) {
        if (AMODE == 1) {
            const int wb = kt * 16 + kq * 2;
            #pragma unroll
            for (int q = 0; q < 4; q++) {
                sua[q] = *(const uint2*)(pu16[q] + wb);
                sva[q] = *(const uint2*)(pv16[q] + wb);
            }
        } else {
            const int kb = kt * 32 + kq * 4;
            #pragma unroll
            for (int q = 0; q < 4; q++)
                sau[q] = *(const float4*)(pa32[q] + kb);
        }
    };

    auto sts_a = [&](int kt) {
        u32* base = abuf(kt);
        const int kt2  = kq >> 2;
        const int kk16 = (kq & 3) * 4;
        const int regk = kk16 >> 3;
        const int t0   = (kk16 & 7) >> 1;
        const __half2 hz = __float2half2_rn(0.f);
        #pragma unroll
        for (int q = 0; q < 4; q++) {
            const int ml = lr8 + 32 * q;
            const int mt = ml >> 4;
            const int rr = ml & 15;
            const int g  = rr & 7;
            const int reg = (rr >> 3) + 2 * regk;
            u32* sub = base + (mt * 2 + kt2) * SUB_A;
            u32 w0, w1;
            if (AMODE == 1) {
                __half2 u0 = *(const __half2*)&sua[q].x;
                __half2 u1 = *(const __half2*)&sua[q].y;
                __half2 v0 = *(const __half2*)&sva[q].x;
                __half2 v1 = *(const __half2*)&sva[q].y;
                __half2 r0 = __hmax2(__hadd2(u0, v0), hz);
                __half2 r1 = __hmax2(__hadd2(u1, v1), hz);
                w0 = *(u32*)&r0; w1 = *(u32*)&r1;
            } else {
                w0 = h2pack(sau[q].x, sau[q].y);
                w1 = h2pack(sau[q].z, sau[q].w);
            }
            sub[(g * 4 + t0)     * 4 + reg] = w0;
            sub[(g * 4 + t0 + 1) * 4 + reg] = w1;
        }
    };

    float acc[2][8][4] = {};

    cp_issue(0); cp_issue(1); cp_issue(2);
    if (AMODE != 3) { ldg_a(0); sts_a(0); }

    for (int kt = 0; kt < 16; kt++) {
        cp_wait<2>();
        __syncthreads();
        cp_issue(kt + 3);
        if (AMODE != 3 && kt < 15) { ldg_a(kt + 1); sts_a(kt + 1); }

        const u32* ab = abuf(kt);
        const u32* bb = bbuf(kt);
        #pragma unroll
        for (int kt2 = 0; kt2 < 2; kt2++) {
            uint4 af0 = *(const uint4*)(ab + ((wm * 2 + 0) * 2 + kt2) * SUB_A + lane * 4);
            uint4 af1 = *(const uint4*)(ab + ((wm * 2 + 1) * 2 + kt2) * SUB_A + lane * 4);
            const u32* bl = bb + kt2 * B_KT2 + lane * 36 + wn * 16;
            u32 bfs[16];
            *(uint4*)(bfs + 0)  = *(const uint4*)(bl + 0);
            *(uint4*)(bfs + 4)  = *(const uint4*)(bl + 4);
            *(uint4*)(bfs + 8)  = *(const uint4*)(bl + 8);
            *(uint4*)(bfs + 12) = *(const uint4*)(bl + 12);
            #pragma unroll
            for (int j = 0; j < 8; j++) {
                mma16(acc[0][j], (const u32*)&af0, bfs + j * 2);
                mma16(acc[1][j], (const u32*)&af1, bfs + j * 2);
            }
        }
    }

    const int cbase = n0e + wn * 64 + (lane & 3) * 2;

    if (EPI == 1) {
        const int s = by % 5;
        float csum[8][2];
        #pragma unroll
        for (int j = 0; j < 8; j++) { csum[j][0] = 0.f; csum[j][1] = 0.f; }
        #pragma unroll
        for (int i = 0; i < 2; i++) {
            #pragma unroll
            for (int hm = 0; hm < 2; hm++) {
                const int ml = wm * 32 + i * 16 + hm * 8 + (lane >> 2);
                const int p  = s * 125 + ml;
                const int ii = p / 25, jj = p - ii * 25;
                if ((ml < 125) && (ii != jj)) {
                    #pragma unroll
                    for (int j = 0; j < 8; j++) {
                        float o0 = acc[i][j][hm * 2 + 0] + beff[cbase + j * 8];
                        float o1 = acc[i][j][hm * 2 + 1] + beff[cbase + j * 8 + 1];
                        csum[j][0] += fmaxf(o0, 0.f);
                        csum[j][1] += fmaxf(o1, 0.f);
                    }
                }
            }
        }
        #pragma unroll
        for (int j = 0; j < 8; j++)
            #pragma unroll
            for (int c = 0; c < 2; c++) {
                float v = csum[j][c];
                v += __shfl_xor_sync(0xffffffffu, v, 4);
                v += __shfl_xor_sync(0xffffffffu, v, 8);
                v += __shfl_xor_sync(0xffffffffu, v, 16);
                csum[j][c] = v;
            }
        __syncthreads();
        float* red = (float*)smem;
        if ((lane >> 2) == 0) {
            #pragma unroll
            for (int j = 0; j < 8; j++) {
                red[wm * 128 + wn * 64 + j * 8 + (lane & 3) * 2 + 0] = csum[j][0];
                red[wm * 128 + wn * 64 + j * 8 + (lane & 3) * 2 + 1] = csum[j][1];
            }
        }
        __syncthreads();
        if (tid < 128) {
            float v = red[tid] + red[128 + tid] + red[256 + tid] + red[384 + tid];
            Cdst[(size_t)by * 512 + n0e + tid] = v;
        }
        return;
    }

    if (EPI == 2) {
        __syncthreads();
        #pragma unroll
        for (int i = 0; i < 2; i++) {
            #pragma unroll
            for (int hm = 0; hm < 2; hm++) {
                const int ml = wm * 32 + i * 16 + hm * 8 + (lane >> 2);
                if (ml >= 125) continue;
                const int mt = ml >> 4;
                const int rr = ml & 15;
                const int g  = rr & 7;
                const int regm = rr >> 3;
                #pragma unroll
                for (int j = 0; j < 8; j++) {
                    const int nL  = wn * 64 + j * 8 + (lane & 3) * 2;
                    const int kk  = nL & 15;
                    float o0 = acc[i][j][hm * 2 + 0] + beff[n0e + nL];
                    float o1 = acc[i][j][hm * 2 + 1] + beff[n0e + nL + 1];
                    smem[(nL >> 5) * ATILE + ((mt * 2 + ((nL >> 4) & 1)) * SUB_A)
                         + (g * 4 + ((kk & 7) >> 1)) * 4 + regm + 2 * (kk >> 3)]
                        = h2pack(fmaxf(o0, 0.f), fmaxf(o1, 0.f));
                }
            }
        }
        __syncthreads();
        u32* dst = g_Himg + ((size_t)by * 16 + bx * 4) * ATILE;
        for (int t = tid; t < ATILE; t += 256)
            *(uint4*)(dst + t * 4) = *(const uint4*)(smem + t * 4);
        return;
    }

    if (EPI == 3) {
        u32* dstw = (u32*)Cdst;
        const int wbase = (n0e >> 1) + wn * 32 + (lane & 3);
        #pragma unroll
        for (int i = 0; i < 2; i++) {
            #pragma unroll
            for (int hm = 0; hm < 2; hm++) {
                const int ml = wm * 32 + i * 16 + hm * 8 + (lane >> 2);
                if (ml >= row_cap) continue;
                u32* rowp = dstw + (row_base + ml) * 256 + wbase;
                #pragma unroll
                for (int j = 0; j < 8; j++) {
                    float o0 = acc[i][j][hm * 2 + 0];
                    float o1 = acc[i][j][hm * 2 + 1];
                    if (beff) {
                        o0 += beff[cbase + j * 8];
                        o1 += beff[cbase + j * 8 + 1];
                    }
                    rowp[j * 4] = h2pack(o0, o1);
                }
            }
        }
        return;
    }
}

// ======================================================================
// head FC body: 256 threads = 4 k-groups x 64 n-lanes
// ======================================================================
template<int AGG, int RELU>
__device__ __forceinline__
void head_body(int bx, int by, const float* __restrict__ X,
               const float* __restrict__ W, const float* __restrict__ bias,
               float* __restrict__ Y, int Nout, u32* smem_)
{
    float* xs  = (float*)smem_;
    float* red = xs + 512;

    const int b   = by;
    const int n0  = bx * 64;
    const int tid = threadIdx.x;
    const int nl  = tid & 63;
    const int kg  = tid >> 6;

    #pragma unroll
    for (int t = 0; t < 2; t++) {
        const int k = tid + t * 256;
        if (AGG) {
            const float* p = g_PART + (size_t)(b * 5) * 512 + k;
            xs[k] = p[0] + p[512] + p[1024] + p[1536] + p[2048];
        } else {
            xs[k] = X[(size_t)b * 512 + k];
        }
    }
    __syncthreads();

    const int n = n0 + nl;
    float acc = 0.f;
    if (n < Nout) {
        const float* wp = W + (size_t)(kg * 128) * Nout + n;
        #pragma unroll 8
        for (int kk = 0; kk < 128; kk++)
            acc = fmaf(xs[kg * 128 + kk], wp[(size_t)kk * Nout], acc);
    }
    red[kg * 64 + nl] = acc;
    __syncthreads();
    if (kg == 0 && n < Nout) {
        float v = red[nl] + red[64 + nl] + red[128 + nl] + red[192 + nl] + bias[n];
        if (RELU) v = fmaxf(v, 0.f);
        Y[(size_t)b * Nout + n] = v;
    }
}

// ======================================================================
// fused pipeline kernel: roles by blockIdx (forward-only flag deps)
//   [0,56)      UV        (releases flag 0)
//   [56,696)    h2        (waits 0==56; releases 8+by)
//   [696,1336)  h3+reduce (waits 8+by==4; releases 1)
//   [1336,1592) head1     (waits 1==640; releases 2)
//   [1592,1848) head2     (waits 2==256; releases 3)
//   [1848,2360) head3     (waits 3==256)
// ======================================================================
__global__ __launch_bounds__(256, 2)
void fused_pipeline(const float* __restrict__ x,
                    const float* __restrict__ g_b1, const float* __restrict__ g_b2,
                    const float* __restrict__ g_b3,
                    const float* __restrict__ f_w1, const float* __restrict__ f_b1,
                    const float* __restrict__ f_w2, const float* __restrict__ f_b2,
                    const float* __restrict__ f_w3, const float* __restrict__ f_b3,
                    float* __restrict__ out)
{
    extern __shared__ u32 smem[];
    const int bid = blockIdx.x;

    if (bid < 56) {
        gemm_body<2,3,0>(bid & 7, bid >> 3, x, g_W1img, g_b1,
                         (float*)g_Uh, (float*)g_Vh, M_ROWS, smem);
        bump_flag(0);
    } else if (bid < 696) {
        const int t = bid - 56;
        wait_flag(0, 56);
        gemm_body<1,2,1>(t & 3, t >> 2, nullptr, g_W2img, g_b2,
                         nullptr, nullptr, 0, smem);
        bump_flag(8 + (t >> 2));
    } else if (bid < 1336) {
        const int t = bid - 696;
        wait_flag(8 + (t >> 2), 4);
        gemm_body<3,1,1>(t & 3, t >> 2, nullptr, g_W3img, g_b3,
                         g_PART, nullptr, 0, smem);
        bump_flag(1);
    } else if (bid < 1592) {
        const int t = bid - 1336;
        wait_flag(1, 640);
        head_body<1,1>(t & 7, t >> 3, nullptr, f_w1, f_b1, g_Z1, 512, smem);
        bump_flag(2);
    } else if (bid < 1848) {
        const int t = bid - 1592;
        wait_flag(2, 256);
        head_body<0,1>(t & 7, t >> 3, g_Z1, f_w2, f_b2, g_Z2, 512, smem);
        bump_flag(3);
    } else {
        const int t = bid - 1848;
        wait_flag(3, 256);
        head_body<0,0>(t & 15, t >> 4, g_Z2, f_w3, f_b3, out, C_, smem);
    }
}

// ======================================================================
extern "C" void kernel_launch(void* const* d_in, const int* in_sizes, int n_in,
                              void* d_out, int out_size)
{
    const float* x    = (const float*)d_in[0];
    const float* g_w1 = (const float*)d_in[1];
    const float* g_b1 = (const float*)d_in[2];
    const float* g_w2 = (const float*)d_in[3];
    const float* g_b2 = (const float*)d_in[4];
    const float* g_w3 = (const float*)d_in[5];
    const float* g_b3 = (const float*)d_in[6];
    const float* f_w1 = (const float*)d_in[7];
    const float* f_b1 = (const float*)d_in[8];
    const float* f_w2 = (const float*)d_in[9];
    const float* f_b2 = (const float*)d_in[10];
    const float* f_w3 = (const float*)d_in[11];
    const float* f_b3 = (const float*)d_in[12];
    float* out = (float*)d_out;

    cudaFuncSetAttribute(fused_pipeline,
                         cudaFuncAttributeMaxDynamicSharedMemorySize, SMEM_AB4);

    // repack all g-network weights into fp16 fragment images (+flag reset)
    repack_w<<<2048, 256>>>(g_w1, g_w1 + 512 * 512, g_w2, g_w3);

    // the whole rest of the network in one bid-ordered launch
    fused_pipeline<<<2360, 256, SMEM_AB4>>>(x, g_b1, g_b2, g_b3,
                                            f_w1, f_b1, f_w2, f_b2, f_w3, f_b3,
                                            out);
}

// round 11
// speedup vs baseline: 1.0464x; 1.0464x over previous
#include <cuda_runtime.h>
#include <cuda_fp16.h>

typedef unsigned int u32;

namespace {
constexpr int B_ = 32, N_ = 25, H_ = 512, C_ = 1000;
constexpr int NP      = N_ * N_;   // 625
constexpr int M_ROWS  = B_ * N_;   // 800

// fp16 fragment-image geometry (u32 words)
constexpr int SUB_A   = 132;                   // 16m x 16k subtile (128 + pad)
constexpr int ATILE   = 16 * SUB_A;            // 2112 u32 per 128m x 32k chunk
constexpr int B_KT2   = 32 * 36;               // 1152
constexpr int BTILE   = 2 * B_KT2;             // 2304 u32 per 128n x 32k chunk

constexpr int STAGE     = ATILE + BTILE;       // 4416 u32 per ring stage
constexpr int SMEM_RING = 6 * STAGE * 4;       // 105984 B (6-stage ring)
}

// ---------------- scratch (allocation-free device globals) ----------------
__device__ u32   g_Uh[M_ROWS * 256];                 // U fp16-packed rows (+b1)
__device__ u32   g_Vh[M_ROWS * 256];                 // V fp16-packed rows
__device__ u32   g_Himg[(size_t)160 * 16 * ATILE];   // h2 as fp16 A-frag image
__device__ u32   g_W1img[2 * 64 * BTILE];            // W1 top + bottom images
__device__ u32   g_W2img[64 * BTILE];
__device__ u32   g_W3img[64 * BTILE];
__device__ float g_PART[160 * H_];
__device__ float g_Z1 [B_ * H_];
__device__ float g_Z2 [B_ * H_];

// ---------------- helpers ----------------
__device__ __forceinline__ u32 h2pack(float lo, float hi) {
    __half2 h = __floats2half2_rn(lo, hi);
    return *(u32*)&h;
}
__device__ __forceinline__ u32 smem_u32(const void* p) {
    u32 a;
    asm("{ .reg .u64 t; cvta.to.shared.u64 t, %1; cvt.u32.u64 %0, t; }"
        : "=r"(a) : "l"(p));
    return a;
}
__device__ __forceinline__ void cpasync16(u32 saddr, const void* g) {
    asm volatile("cp.async.ca.shared.global [%0], [%1], 16;"
                 :: "r"(saddr), "l"(g) : "memory");
}
__device__ __forceinline__ void cp_commit() {
    asm volatile("cp.async.commit_group;" ::: "memory");
}
template<int NWAIT>
__device__ __forceinline__ void cp_wait() {
    asm volatile("cp.async.wait_group %0;" :: "n"(NWAIT) : "memory");
}
__device__ __forceinline__ void mma16(float* d, const u32* a, const u32* b) {
    asm volatile(
        "mma.sync.aligned.m16n8k16.row.col.f32.f16.f16.f32 "
        "{%0,%1,%2,%3}, {%4,%5,%6,%7}, {%8,%9}, {%0,%1,%2,%3};\n"
        : "+f"(d[0]), "+f"(d[1]), "+f"(d[2]), "+f"(d[3])
        : "r"(a[0]), "r"(a[1]), "r"(a[2]), "r"(a[3]), "r"(b[0]), "r"(b[1]));
}

// ======================================================================
// weight repack: W[k][n] -> fp16 B-fragment image (128n x 32k chunks).
// word = kt2*1152 + lane*36 + (j16>>3)*16 + (j16&7)*2 + reg
// ======================================================================
__global__ void repack_w(const float* __restrict__ w1a, const float* __restrict__ w1b,
                         const float* __restrict__ w2,  const float* __restrict__ w3)
{
    const u32 idx = blockIdx.x * 256 + threadIdx.x;   // 4 * 131072
    const int sel = idx >> 17;
    const int e   = idx & 131071;
    const int k2  = e >> 9;
    const int n   = e & 511;
    const int k0  = k2 * 2;
    const float* src = (sel == 0) ? w1a : (sel == 1) ? w1b : (sel == 2) ? w2 : w3;
    u32* dst = (sel == 0) ? g_W1img
             : (sel == 1) ? g_W1img + 64 * BTILE
             : (sel == 2) ? g_W2img : g_W3img;
    const float v0 = src[(size_t)k0 * 512 + n];
    const float v1 = src[(size_t)(k0 + 1) * 512 + n];
    const int nt  = n >> 7, nn = n & 127;
    const int kt  = k0 >> 5, kt2 = (k0 >> 4) & 1, kk = k0 & 15;
    const int lane = (nn & 7) * 4 + ((kk & 7) >> 1);
    const int j16  = nn >> 3;
    const int word = kt2 * B_KT2 + lane * 36 + (j16 >> 3) * 16 + (j16 & 7) * 2 + (kk >> 3);
    dst[(size_t)(nt * 16 + kt) * BTILE + word] = h2pack(v0, v1);
}

// ======================================================================
// fp16 tensor-core GEMM, 128m x 128n x (16 x 32k).
// 6-stage smem ring, ONE barrier per 64-k pair (8 barriers total).
// AMODE 1: A = relu(Uh_i + Vh_j)   AMODE 2: UV split   AMODE 3: A image
// EPI 0: bias store  EPI 1: masked reduce  EPI 2: -> g_Himg  EPI 3: U/V out
// ======================================================================
template<int AMODE, int EPI, int RT>
__global__ __launch_bounds__(256, 2)
void gemm_tc(const float* __restrict__ A, const u32* __restrict__ Bimg,
             const float* __restrict__ bias, float* __restrict__ C,
             float* __restrict__ C2, int M)
{
    extern __shared__ u32 smem[];
    const u32 sbase = smem_u32(smem);

    const int tid  = threadIdx.x;
    const int lane = tid & 31;
    const int wid  = tid >> 5;
    const int wm   = wid >> 1;
    const int wn   = wid & 1;
    const int by   = blockIdx.y;
    const int bx   = blockIdx.x;

    const u32* bimg = Bimg;
    float*     Cdst = C;
    const float* beff = bias;
    int nt = bx;
    if (AMODE == 2) {
        if (bx >= 4) { bimg = Bimg + 64 * BTILE; Cdst = C2; beff = nullptr; }
        nt = bx & 3;
    }
    const int n0e = nt * 128;

    const int row_base = RT ? (by / 5) * NP + (by % 5) * 125 : by * 128;
    const int row_cap  = RT ? 125 : (M - row_base);

    // ---- register-path A mapping (AMODE 1/2) ----
    const int lr8 = tid >> 3;
    const int kq  = tid & 7;
    const u32*   pu16[4];
    const u32*   pv16[4];
    const float* pa32[4];
    if (AMODE == 1 || AMODE == 2) {
        #pragma unroll
        for (int q = 0; q < 4; q++) {
            const int ml = lr8 + 32 * q;
            int m = row_base + ((ml < row_cap) ? ml : 0);
            if (AMODE == 1) {
                int b = m / NP; int r = m - b * NP;
                int i = r / N_; int j = r - i * N_;
                pu16[q] = g_Uh + (b * N_ + i) * 256;
                pv16[q] = g_Vh + (b * N_ + j) * 256;
            } else {
                pa32[q] = A + (size_t)m * 512;
            }
        }
    }

    uint2  sua[4], sva[4];
    float4 sau[4];

    auto abuf = [&](int kt) -> u32* { return smem + (kt % 6) * STAGE; };

    // one commit group per 64-k pair
    auto cp_issue_pair = [&](int q) {
        #pragma unroll
        for (int d = 0; d < 2; d++) {
            const int kt = q + d;
            if (kt < 16) {
                u32* ab = abuf(kt);
                const u32 sB = sbase + (u32)((ab - smem) + ATILE) * 4;
                const u32* bsrc = bimg + (size_t)(nt * 16 + kt) * BTILE;
                for (int t = tid; t < BTILE / 4; t += 256)
                    cpasync16(sB + t * 16, bsrc + t * 4);
                if (AMODE == 3) {
                    const u32 sA = sbase + (u32)(ab - smem) * 4;
                    const u32* asrc = g_Himg + ((size_t)by * 16 + kt) * ATILE;
                    for (int t = tid; t < ATILE / 4; t += 256)
                        cpasync16(sA + t * 16, asrc + t * 4);
                }
            }
        }
        cp_commit();
    };

    auto ldg_a = [&](int kt) {
        if (AMODE == 1) {
            const int wb = kt * 16 + kq * 2;
            #pragma unroll
            for (int q = 0; q < 4; q++) {
                sua[q] = *(const uint2*)(pu16[q] + wb);
                sva[q] = *(const uint2*)(pv16[q] + wb);
            }
        } else {
            const int kb = kt * 32 + kq * 4;
            #pragma unroll
            for (int q = 0; q < 4; q++)
                sau[q] = *(const float4*)(pa32[q] + kb);
        }
    };

    auto sts_a = [&](int kt) {
        u32* base = abuf(kt);
        const int kt2  = kq >> 2;
        const int kk16 = (kq & 3) * 4;
        const int regk = kk16 >> 3;
        const int t0   = (kk16 & 7) >> 1;
        const __half2 hz = __float2half2_rn(0.f);
        #pragma unroll
        for (int q = 0; q < 4; q++) {
            const int ml = lr8 + 32 * q;
            const int mt = ml >> 4;
            const int rr = ml & 15;
            const int g  = rr & 7;
            const int reg = (rr >> 3) + 2 * regk;
            u32* sub = base + (mt * 2 + kt2) * SUB_A;
            u32 w0, w1;
            if (AMODE == 1) {
                __half2 u0 = *(const __half2*)&sua[q].x;
                __half2 u1 = *(const __half2*)&sua[q].y;
                __half2 v0 = *(const __half2*)&sva[q].x;
                __half2 v1 = *(const __half2*)&sva[q].y;
                __half2 r0 = __hmax2(__hadd2(u0, v0), hz);
                __half2 r1 = __hmax2(__hadd2(u1, v1), hz);
                w0 = *(u32*)&r0; w1 = *(u32*)&r1;
            } else {
                w0 = h2pack(sau[q].x, sau[q].y);
                w1 = h2pack(sau[q].z, sau[q].w);
            }
            sub[(g * 4 + t0)     * 4 + reg] = w0;
            sub[(g * 4 + t0 + 1) * 4 + reg] = w1;
        }
    };

    float acc[2][8][4] = {};

    auto compute = [&](int kt) {
        const u32* ab = abuf(kt);
        const u32* bb = ab + ATILE;
        #pragma unroll
        for (int kt2 = 0; kt2 < 2; kt2++) {
            uint4 af0 = *(const uint4*)(ab + ((wm * 2 + 0) * 2 + kt2) * SUB_A + lane * 4);
            uint4 af1 = *(const uint4*)(ab + ((wm * 2 + 1) * 2 + kt2) * SUB_A + lane * 4);
            const u32* bl = bb + kt2 * B_KT2 + lane * 36 + wn * 16;
            u32 bfs[16];
            *(uint4*)(bfs + 0)  = *(const uint4*)(bl + 0);
            *(uint4*)(bfs + 4)  = *(const uint4*)(bl + 4);
            *(uint4*)(bfs + 8)  = *(const uint4*)(bl + 8);
            *(uint4*)(bfs + 12) = *(const uint4*)(bl + 12);
            #pragma unroll
            for (int j = 0; j < 8; j++) {
                mma16(acc[0][j], (const u32*)&af0, bfs + j * 2);
                mma16(acc[1][j], (const u32*)&af1, bfs + j * 2);
            }
        }
    };

    // prologue: 2 pair-groups in flight; A(0),A(1) via registers
    cp_issue_pair(0);
    cp_issue_pair(2);
    if (AMODE != 3) { ldg_a(0); sts_a(0); ldg_a(1); sts_a(1); }

    for (int q = 0; q < 16; q += 2) {
        cp_wait<1>();                 // pair q landed (pair q+2 may be pending)
        __syncthreads();
        cp_issue_pair(q + 4);         // stages (q+4)%6,(q+5)%6 (= q-2,q-1: done)
        if (AMODE != 3 && q + 2 < 16) {
            ldg_a(q + 2); sts_a(q + 2);
            ldg_a(q + 3); sts_a(q + 3);
        }
        compute(q);
        compute(q + 1);
    }

    const int cbase = n0e + wn * 64 + (lane & 3) * 2;

    if (EPI == 1) {
        // ---- fused masked column reduction (bias+relu first) ----
        const int s = by % 5;
        float csum[8][2];
        #pragma unroll
        for (int j = 0; j < 8; j++) { csum[j][0] = 0.f; csum[j][1] = 0.f; }
        #pragma unroll
        for (int i = 0; i < 2; i++) {
            #pragma unroll
            for (int hm = 0; hm < 2; hm++) {
                const int ml = wm * 32 + i * 16 + hm * 8 + (lane >> 2);
                const int p  = s * 125 + ml;
                const int ii = p / 25, jj = p - ii * 25;
                if ((ml < 125) && (ii != jj)) {
                    #pragma unroll
                    for (int j = 0; j < 8; j++) {
                        float o0 = acc[i][j][hm * 2 + 0] + beff[cbase + j * 8];
                        float o1 = acc[i][j][hm * 2 + 1] + beff[cbase + j * 8 + 1];
                        csum[j][0] += fmaxf(o0, 0.f);
                        csum[j][1] += fmaxf(o1, 0.f);
                    }
                }
            }
        }
        #pragma unroll
        for (int j = 0; j < 8; j++)
            #pragma unroll
            for (int c = 0; c < 2; c++) {
                float v = csum[j][c];
                v += __shfl_xor_sync(0xffffffffu, v, 4);
                v += __shfl_xor_sync(0xffffffffu, v, 8);
                v += __shfl_xor_sync(0xffffffffu, v, 16);
                csum[j][c] = v;
            }
        __syncthreads();
        float* red = (float*)smem;
        if ((lane >> 2) == 0) {
            #pragma unroll
            for (int j = 0; j < 8; j++) {
                red[wm * 128 + wn * 64 + j * 8 + (lane & 3) * 2 + 0] = csum[j][0];
                red[wm * 128 + wn * 64 + j * 8 + (lane & 3) * 2 + 1] = csum[j][1];
            }
        }
        __syncthreads();
        if (tid < 128) {
            float v = red[tid] + red[128 + tid] + red[256 + tid] + red[384 + tid];
            Cdst[(size_t)by * 512 + n0e + tid] = v;
        }
        return;
    }

    if (EPI == 2) {
        // ---- relu+bias -> fp16 A-frag image, staged in smem, coalesced out ----
        __syncthreads();
        #pragma unroll
        for (int i = 0; i < 2; i++) {
            #pragma unroll
            for (int hm = 0; hm < 2; hm++) {
                const int ml = wm * 32 + i * 16 + hm * 8 + (lane >> 2);
                if (ml >= 125) continue;
                const int mt = ml >> 4;
                const int rr = ml & 15;
                const int g  = rr & 7;
                const int regm = rr >> 3;
                #pragma unroll
                for (int j = 0; j < 8; j++) {
                    const int nL  = wn * 64 + j * 8 + (lane & 3) * 2;
                    const int kk  = nL & 15;
                    float o0 = acc[i][j][hm * 2 + 0] + beff[n0e + nL];
                    float o1 = acc[i][j][hm * 2 + 1] + beff[n0e + nL + 1];
                    smem[(nL >> 5) * ATILE + ((mt * 2 + ((nL >> 4) & 1)) * SUB_A)
                         + (g * 4 + ((kk & 7) >> 1)) * 4 + regm + 2 * (kk >> 3)]
                        = h2pack(fmaxf(o0, 0.f), fmaxf(o1, 0.f));
                }
            }
        }
        __syncthreads();
        u32* dst = g_Himg + ((size_t)by * 16 + bx * 4) * ATILE;
        for (int t = tid; t < ATILE; t += 256)
            *(uint4*)(dst + t * 4) = *(const uint4*)(smem + t * 4);
        return;
    }

    if (EPI == 3) {
        // ---- bias (no relu) -> fp16-packed rows (U / V) ----
        u32* dstw = (u32*)Cdst;
        const int wbase = (n0e >> 1) + wn * 32 + (lane & 3);
        #pragma unroll
        for (int i = 0; i < 2; i++) {
            #pragma unroll
            for (int hm = 0; hm < 2; hm++) {
                const int ml = wm * 32 + i * 16 + hm * 8 + (lane >> 2);
                if (ml >= row_cap) continue;
                u32* rowp = dstw + (row_base + ml) * 256 + wbase;
                #pragma unroll
                for (int j = 0; j < 8; j++) {
                    float o0 = acc[i][j][hm * 2 + 0];
                    float o1 = acc[i][j][hm * 2 + 1];
                    if (beff) {
                        o0 += beff[cbase + j * 8];
                        o1 += beff[cbase + j * 8 + 1];
                    }
                    rowp[j * 4] = h2pack(o0, o1);
                }
            }
        }
        return;
    }

    // ---- EPI 0: bias store (fp32) ----
    #pragma unroll
    for (int i = 0; i < 2; i++) {
        #pragma unroll
        for (int hm = 0; hm < 2; hm++) {
            const int ml = wm * 32 + i * 16 + hm * 8 + (lane >> 2);
            if (ml >= row_cap) continue;
            float* outp = Cdst + (size_t)(row_base + ml) * 512 + cbase;
            #pragma unroll
            for (int j = 0; j < 8; j++) {
                float o0 = acc[i][j][hm * 2 + 0];
                float o1 = acc[i][j][hm * 2 + 1];
                if (beff) {
                    o0 += beff[cbase + j * 8];
                    o1 += beff[cbase + j * 8 + 1];
                }
                *(float2*)(outp + j * 8) = make_float2(o0, o1);
            }
        }
    }
}

// ======================================================================
// Head FC layer: grid (n-tiles of 64, 32 b), block 512 = 8 k-groups x 64.
// ======================================================================
template<int AGG, int RELU>
__global__ __launch_bounds__(512)
void head_fc(const float* __restrict__ X, const float* __restrict__ W,
             const float* __restrict__ bias, float* __restrict__ Y, int Nout)
{
    __shared__ float xs[512];
    __shared__ float red[8][64];

    const int b   = blockIdx.y;
    const int n0  = blockIdx.x * 64;
    const int tid = threadIdx.x;
    const int nl  = tid & 63;
    const int kg  = tid >> 6;

    if (AGG) {
        const float* p = g_PART + (size_t)(b * 5) * 512 + tid;
        xs[tid] = p[0] + p[512] + p[1024] + p[1536] + p[2048];
    } else {
        xs[tid] = X[(size_t)b * 512 + tid];
    }
    __syncthreads();

    const int n = n0 + nl;
    float acc = 0.f;
    if (n < Nout) {
        const float* wp = W + (size_t)(kg * 64) * Nout + n;
        #pragma unroll 16
        for (int kk = 0; kk < 64; kk++)
            acc = fmaf(xs[kg * 64 + kk], wp[(size_t)kk * Nout], acc);
    }
    red[kg][nl] = acc;
    __syncthreads();
    if (kg == 0 && n < Nout) {
        float v = bias[n];
        #pragma unroll
        for (int g = 0; g < 8; g++) v += red[g][nl];
        if (RELU) v = fmaxf(v, 0.f);
        Y[(size_t)b * Nout + n] = v;
    }
}

// ======================================================================
extern "C" void kernel_launch(void* const* d_in, const int* in_sizes, int n_in,
                              void* d_out, int out_size)
{
    const float* x    = (const float*)d_in[0];
    const float* g_w1 = (const float*)d_in[1];
    const float* g_b1 = (const float*)d_in[2];
    const float* g_w2 = (const float*)d_in[3];
    const float* g_b2 = (const float*)d_in[4];
    const float* g_w3 = (const float*)d_in[5];
    const float* g_b3 = (const float*)d_in[6];
    const float* f_w1 = (const float*)d_in[7];
    const float* f_b1 = (const float*)d_in[8];
    const float* f_w2 = (const float*)d_in[9];
    const float* f_b2 = (const float*)d_in[10];
    const float* f_w3 = (const float*)d_in[11];
    const float* f_b3 = (const float*)d_in[12];
    float* out = (float*)d_out;

    float *pPART, *pZ1, *pZ2;
    u32 *pW1i, *pW2i, *pW3i, *pUh, *pVh;
    cudaGetSymbolAddress((void**)&pPART, g_PART);
    cudaGetSymbolAddress((void**)&pZ1,   g_Z1);
    cudaGetSymbolAddress((void**)&pZ2,   g_Z2);
    cudaGetSymbolAddress((void**)&pW1i,  g_W1img);
    cudaGetSymbolAddress((void**)&pW2i,  g_W2img);
    cudaGetSymbolAddress((void**)&pW3i,  g_W3img);
    cudaGetSymbolAddress((void**)&pUh,   g_Uh);
    cudaGetSymbolAddress((void**)&pVh,   g_Vh);

    cudaFuncSetAttribute(gemm_tc<2,3,0>, cudaFuncAttributeMaxDynamicSharedMemorySize, SMEM_RING);
    cudaFuncSetAttribute(gemm_tc<1,2,1>, cudaFuncAttributeMaxDynamicSharedMemorySize, SMEM_RING);
    cudaFuncSetAttribute(gemm_tc<3,1,1>, cudaFuncAttributeMaxDynamicSharedMemorySize, SMEM_RING);

    // repack all g-network weights into fp16 fragment images
    repack_w<<<2048, 256>>>(g_w1, g_w1 + 512 * 512, g_w2, g_w3);

    // U | V in one launch -> fp16-packed rows (x>=4 -> W1 bottom, V out)
    gemm_tc<2,3,0><<<dim3(8, 7), 256, SMEM_RING>>>(x, pW1i, g_b1,
                                                   (float*)pUh, (float*)pVh, M_ROWS);

    // h2 = relu(relu(U_i+V_j) @ W2 + b2) -> fp16 A-fragment image
    gemm_tc<1,2,1><<<dim3(4, 160), 256, SMEM_RING>>>(nullptr, pW2i, g_b2,
                                                     nullptr, nullptr, 0);

    // h3 GEMM (A,B via cp.async images) fused with masked pair reduction
    gemm_tc<3,1,1><<<dim3(4, 160), 256, SMEM_RING>>>(nullptr, pW3i, g_b3,
                                                     pPART, nullptr, 0);

    // f head
    head_fc<1,1><<<dim3(8,  B_), 512>>>(nullptr, f_w1, f_b1, pZ1, 512);
    head_fc<0,1><<<dim3(8,  B_), 512>>>(pZ1,     f_w2, f_b2, pZ2, 512);
    head_fc<0,0><<<dim3(16, B_), 512>>>(pZ2,     f_w3, f_b3, out, C_);
}

// round 12
// speedup vs baseline: 1.0617x; 1.0147x over previous
#include <cuda_runtime.h>
#include <cuda_fp16.h>

typedef unsigned int u32;

namespace {
constexpr int B_ = 32, N_ = 25, H_ = 512, C_ = 1000;
constexpr int NP      = N_ * N_;   // 625
constexpr int M_ROWS  = B_ * N_;   // 800

// fp16 fragment-image geometry (u32 words)
constexpr int SUB_A   = 132;                   // 16m x 16k subtile (128 + pad)
constexpr int ATILE   = 16 * SUB_A;            // 2112 u32 per 128m x 32k chunk
constexpr int B_KT2   = 32 * 36;               // 1152
constexpr int BTILE   = 2 * B_KT2;             // 2304 u32 per 128n x 32k chunk

constexpr int STAGE     = ATILE + BTILE;       // 4416 u32 per ring stage
constexpr int SMEM_RING = 6 * STAGE * 4;       // 105984 B (6-stage ring)
}

// ---------------- scratch (allocation-free device globals) ----------------
__device__ u32   g_Uh[M_ROWS * 256];                 // U fp16-packed rows (+b1)
__device__ u32   g_Vh[M_ROWS * 256];                 // V fp16-packed rows
__device__ u32   g_Himg[(size_t)160 * 16 * ATILE];   // h2 as fp16 A-frag image
__device__ u32   g_W1img[2 * 64 * BTILE];            // W1 top + bottom images
__device__ u32   g_W2img[64 * BTILE];
__device__ u32   g_W3img[64 * BTILE];
__device__ float g_PART[160 * H_];
__device__ float g_Z1 [B_ * H_];
__device__ float g_Z2 [B_ * H_];

// ---------------- helpers ----------------
__device__ __forceinline__ u32 h2pack(float lo, float hi) {
    __half2 h = __floats2half2_rn(lo, hi);
    return *(u32*)&h;
}
__device__ __forceinline__ u32 smem_u32(const void* p) {
    u32 a;
    asm("{ .reg .u64 t; cvta.to.shared.u64 t, %1; cvt.u32.u64 %0, t; }"
        : "=r"(a) : "l"(p));
    return a;
}
__device__ __forceinline__ void cpasync16(u32 saddr, const void* g) {
    asm volatile("cp.async.ca.shared.global [%0], [%1], 16;"
                 :: "r"(saddr), "l"(g) : "memory");
}
__device__ __forceinline__ void cp_commit() {
    asm volatile("cp.async.commit_group;" ::: "memory");
}
template<int NWAIT>
__device__ __forceinline__ void cp_wait() {
    asm volatile("cp.async.wait_group %0;" :: "n"(NWAIT) : "memory");
}
__device__ __forceinline__ void mma16(float* d, const u32* a, const u32* b) {
    asm volatile(
        "mma.sync.aligned.m16n8k16.row.col.f32.f16.f16.f32 "
        "{%0,%1,%2,%3}, {%4,%5,%6,%7}, {%8,%9}, {%0,%1,%2,%3};\n"
        : "+f"(d[0]), "+f"(d[1]), "+f"(d[2]), "+f"(d[3])
        : "r"(a[0]), "r"(a[1]), "r"(a[2]), "r"(a[3]), "r"(b[0]), "r"(b[1]));
}

// ======================================================================
// weight repack: W[k][n] -> fp16 B-fragment image (128n x 32k chunks).
// word = kt2*1152 + lane*36 + (j16>>3)*16 + (j16&7)*2 + reg
// ======================================================================
__global__ void repack_w(const float* __restrict__ w1a, const float* __restrict__ w1b,
                         const float* __restrict__ w2,  const float* __restrict__ w3)
{
    const u32 idx = blockIdx.x * 256 + threadIdx.x;   // 4 * 131072
    const int sel = idx >> 17;
    const int e   = idx & 131071;
    const int k2  = e >> 9;
    const int n   = e & 511;
    const int k0  = k2 * 2;
    const float* src = (sel == 0) ? w1a : (sel == 1) ? w1b : (sel == 2) ? w2 : w3;
    u32* dst = (sel == 0) ? g_W1img
             : (sel == 1) ? g_W1img + 64 * BTILE
             : (sel == 2) ? g_W2img : g_W3img;
    const float v0 = src[(size_t)k0 * 512 + n];
    const float v1 = src[(size_t)(k0 + 1) * 512 + n];
    const int nt  = n >> 7, nn = n & 127;
    const int kt  = k0 >> 5, kt2 = (k0 >> 4) & 1, kk = k0 & 15;
    const int lane = (nn & 7) * 4 + ((kk & 7) >> 1);
    const int j16  = nn >> 3;
    const int word = kt2 * B_KT2 + lane * 36 + (j16 >> 3) * 16 + (j16 & 7) * 2 + (kk >> 3);
    dst[(size_t)(nt * 16 + kt) * BTILE + word] = h2pack(v0, v1);
}

// ======================================================================
// fp16 tensor-core GEMM, 128m x 128n x (16 x 32k).
// 6-stage smem ring, ONE barrier per 64-k pair (8 barriers total).
// AMODE 1: A = relu(Uh_i + Vh_j)   AMODE 2: UV split   AMODE 3: A image
// EPI 0: bias store  EPI 1: masked reduce  EPI 2: -> g_Himg  EPI 3: U/V out
// ======================================================================
template<int AMODE, int EPI, int RT>
__global__ __launch_bounds__(256, 2)
void gemm_tc(const float* __restrict__ A, const u32* __restrict__ Bimg,
             const float* __restrict__ bias, float* __restrict__ C,
             float* __restrict__ C2, int M)
{
    extern __shared__ u32 smem[];
    const u32 sbase = smem_u32(smem);

    const int tid  = threadIdx.x;
    const int lane = tid & 31;
    const int wid  = tid >> 5;
    const int wm   = wid >> 1;
    const int wn   = wid & 1;
    const int by   = blockIdx.y;
    const int bx   = blockIdx.x;

    const u32* bimg = Bimg;
    float*     Cdst = C;
    const float* beff = bias;
    int nt = bx;
    if (AMODE == 2) {
        if (bx >= 4) { bimg = Bimg + 64 * BTILE; Cdst = C2; beff = nullptr; }
        nt = bx & 3;
    }
    const int n0e = nt * 128;

    const int row_base = RT ? (by / 5) * NP + (by % 5) * 125 : by * 128;
    const int row_cap  = RT ? 125 : (M - row_base);

    // ---- register-path A mapping (AMODE 1/2) ----
    const int lr8 = tid >> 3;
    const int kq  = tid & 7;
    const u32*   pu16[4];
    const u32*   pv16[4];
    const float* pa32[4];
    if (AMODE == 1 || AMODE == 2) {
        #pragma unroll
        for (int q = 0; q < 4; q++) {
            const int ml = lr8 + 32 * q;
            int m = row_base + ((ml < row_cap) ? ml : 0);
            if (AMODE == 1) {
                int b = m / NP; int r = m - b * NP;
                int i = r / N_; int j = r - i * N_;
                pu16[q] = g_Uh + (b * N_ + i) * 256;
                pv16[q] = g_Vh + (b * N_ + j) * 256;
            } else {
                pa32[q] = A + (size_t)m * 512;
            }
        }
    }

    uint2  sua[4], sva[4];
    float4 sau[4];

    auto abuf = [&](int kt) -> u32* { return smem + (kt % 6) * STAGE; };

    // one commit group per 64-k pair
    auto cp_issue_pair = [&](int q) {
        #pragma unroll
        for (int d = 0; d < 2; d++) {
            const int kt = q + d;
            if (kt < 16) {
                u32* ab = abuf(kt);
                const u32 sB = sbase + (u32)((ab - smem) + ATILE) * 4;
                const u32* bsrc = bimg + (size_t)(nt * 16 + kt) * BTILE;
                for (int t = tid; t < BTILE / 4; t += 256)
                    cpasync16(sB + t * 16, bsrc + t * 4);
                if (AMODE == 3) {
                    const u32 sA = sbase + (u32)(ab - smem) * 4;
                    const u32* asrc = g_Himg + ((size_t)by * 16 + kt) * ATILE;
                    for (int t = tid; t < ATILE / 4; t += 256)
                        cpasync16(sA + t * 16, asrc + t * 4);
                }
            }
        }
        cp_commit();
    };

    auto ldg_a = [&](int kt) {
        if (AMODE == 1) {
            const int wb = kt * 16 + kq * 2;
            #pragma unroll
            for (int q = 0; q < 4; q++) {
                sua[q] = *(const uint2*)(pu16[q] + wb);
                sva[q] = *(const uint2*)(pv16[q] + wb);
            }
        } else {
            const int kb = kt * 32 + kq * 4;
            #pragma unroll
            for (int q = 0; q < 4; q++)
                sau[q] = *(const float4*)(pa32[q] + kb);
        }
    };

    auto sts_a = [&](int kt) {
        u32* base = abuf(kt);
        const int kt2  = kq >> 2;
        const int kk16 = (kq & 3) * 4;
        const int regk = kk16 >> 3;
        const int t0   = (kk16 & 7) >> 1;
        const __half2 hz = __float2half2_rn(0.f);
        #pragma unroll
        for (int q = 0; q < 4; q++) {
            const int ml = lr8 + 32 * q;
            const int mt = ml >> 4;
            const int rr = ml & 15;
            const int g  = rr & 7;
            const int reg = (rr >> 3) + 2 * regk;
            u32* sub = base + (mt * 2 + kt2) * SUB_A;
            u32 w0, w1;
            if (AMODE == 1) {
                __half2 u0 = *(const __half2*)&sua[q].x;
                __half2 u1 = *(const __half2*)&sua[q].y;
                __half2 v0 = *(const __half2*)&sva[q].x;
                __half2 v1 = *(const __half2*)&sva[q].y;
                __half2 r0 = __hmax2(__hadd2(u0, v0), hz);
                __half2 r1 = __hmax2(__hadd2(u1, v1), hz);
                w0 = *(u32*)&r0; w1 = *(u32*)&r1;
            } else {
                w0 = h2pack(sau[q].x, sau[q].y);
                w1 = h2pack(sau[q].z, sau[q].w);
            }
            sub[(g * 4 + t0)     * 4 + reg] = w0;
            sub[(g * 4 + t0 + 1) * 4 + reg] = w1;
        }
    };

    float acc[2][8][4] = {};

    auto compute = [&](int kt) {
        const u32* ab = abuf(kt);
        const u32* bb = ab + ATILE;
        #pragma unroll
        for (int kt2 = 0; kt2 < 2; kt2++) {
            uint4 af0 = *(const uint4*)(ab + ((wm * 2 + 0) * 2 + kt2) * SUB_A + lane * 4);
            uint4 af1 = *(const uint4*)(ab + ((wm * 2 + 1) * 2 + kt2) * SUB_A + lane * 4);
            const u32* bl = bb + kt2 * B_KT2 + lane * 36 + wn * 16;
            u32 bfs[16];
            *(uint4*)(bfs + 0)  = *(const uint4*)(bl + 0);
            *(uint4*)(bfs + 4)  = *(const uint4*)(bl + 4);
            *(uint4*)(bfs + 8)  = *(const uint4*)(bl + 8);
            *(uint4*)(bfs + 12) = *(const uint4*)(bl + 12);
            #pragma unroll
            for (int j = 0; j < 8; j++) {
                mma16(acc[0][j], (const u32*)&af0, bfs + j * 2);
                mma16(acc[1][j], (const u32*)&af1, bfs + j * 2);
            }
        }
    };

    // prologue: 2 pair-groups in flight; A(0),A(1) via registers
    cp_issue_pair(0);
    cp_issue_pair(2);
    if (AMODE != 3) { ldg_a(0); sts_a(0); ldg_a(1); sts_a(1); }

    for (int q = 0; q < 16; q += 2) {
        cp_wait<1>();                 // pair q landed (pair q+2 may be pending)
        __syncthreads();
        cp_issue_pair(q + 4);         // stages (q+4)%6,(q+5)%6 (= q-2,q-1: done)
        if (AMODE != 3 && q + 2 < 16) {
            ldg_a(q + 2); sts_a(q + 2);
            ldg_a(q + 3); sts_a(q + 3);
        }
        compute(q);
        compute(q + 1);
    }

    const int cbase = n0e + wn * 64 + (lane & 3) * 2;

    if (EPI == 1) {
        // ---- fused masked column reduction (bias+relu first) ----
        const int s = by % 5;
        float csum[8][2];
        #pragma unroll
        for (int j = 0; j < 8; j++) { csum[j][0] = 0.f; csum[j][1] = 0.f; }
        #pragma unroll
        for (int i = 0; i < 2; i++) {
            #pragma unroll
            for (int hm = 0; hm < 2; hm++) {
                const int ml = wm * 32 + i * 16 + hm * 8 + (lane >> 2);
                const int p  = s * 125 + ml;
                const int ii = p / 25, jj = p - ii * 25;
                if ((ml < 125) && (ii != jj)) {
                    #pragma unroll
                    for (int j = 0; j < 8; j++) {
                        float o0 = acc[i][j][hm * 2 + 0] + beff[cbase + j * 8];
                        float o1 = acc[i][j][hm * 2 + 1] + beff[cbase + j * 8 + 1];
                        csum[j][0] += fmaxf(o0, 0.f);
                        csum[j][1] += fmaxf(o1, 0.f);
                    }
                }
            }
        }
        #pragma unroll
        for (int j = 0; j < 8; j++)
            #pragma unroll
            for (int c = 0; c < 2; c++) {
                float v = csum[j][c];
                v += __shfl_xor_sync(0xffffffffu, v, 4);
                v += __shfl_xor_sync(0xffffffffu, v, 8);
                v += __shfl_xor_sync(0xffffffffu, v, 16);
                csum[j][c] = v;
            }
        __syncthreads();
        float* red = (float*)smem;
        if ((lane >> 2) == 0) {
            #pragma unroll
            for (int j = 0; j < 8; j++) {
                red[wm * 128 + wn * 64 + j * 8 + (lane & 3) * 2 + 0] = csum[j][0];
                red[wm * 128 + wn * 64 + j * 8 + (lane & 3) * 2 + 1] = csum[j][1];
            }
        }
        __syncthreads();
        if (tid < 128) {
            float v = red[tid] + red[128 + tid] + red[256 + tid] + red[384 + tid];
            Cdst[(size_t)by * 512 + n0e + tid] = v;
        }
        return;
    }

    if (EPI == 2) {
        // ---- relu+bias -> fp16 A-frag image, staged in smem, coalesced out ----
        __syncthreads();
        #pragma unroll
        for (int i = 0; i < 2; i++) {
            #pragma unroll
            for (int hm = 0; hm < 2; hm++) {
                const int ml = wm * 32 + i * 16 + hm * 8 + (lane >> 2);
                if (ml >= 125) continue;
                const int mt = ml >> 4;
                const int rr = ml & 15;
                const int g  = rr & 7;
                const int regm = rr >> 3;
                #pragma unroll
                for (int j = 0; j < 8; j++) {
                    const int nL  = wn * 64 + j * 8 + (lane & 3) * 2;
                    const int kk  = nL & 15;
                    float o0 = acc[i][j][hm * 2 + 0] + beff[n0e + nL];
                    float o1 = acc[i][j][hm * 2 + 1] + beff[n0e + nL + 1];
                    smem[(nL >> 5) * ATILE + ((mt * 2 + ((nL >> 4) & 1)) * SUB_A)
                         + (g * 4 + ((kk & 7) >> 1)) * 4 + regm + 2 * (kk >> 3)]
                        = h2pack(fmaxf(o0, 0.f), fmaxf(o1, 0.f));
                }
            }
        }
        __syncthreads();
        u32* dst = g_Himg + ((size_t)by * 16 + bx * 4) * ATILE;
        for (int t = tid; t < ATILE; t += 256)
            *(uint4*)(dst + t * 4) = *(const uint4*)(smem + t * 4);
        return;
    }

    if (EPI == 3) {
        // ---- bias (no relu) -> fp16-packed rows (U / V) ----
        u32* dstw = (u32*)Cdst;
        const int wbase = (n0e >> 1) + wn * 32 + (lane & 3);
        #pragma unroll
        for (int i = 0; i < 2; i++) {
            #pragma unroll
            for (int hm = 0; hm < 2; hm++) {
                const int ml = wm * 32 + i * 16 + hm * 8 + (lane >> 2);
                if (ml >= row_cap) continue;
                u32* rowp = dstw + (row_base + ml) * 256 + wbase;
                #pragma unroll
                for (int j = 0; j < 8; j++) {
                    float o0 = acc[i][j][hm * 2 + 0];
                    float o1 = acc[i][j][hm * 2 + 1];
                    if (beff) {
                        o0 += beff[cbase + j * 8];
                        o1 += beff[cbase + j * 8 + 1];
                    }
                    rowp[j * 4] = h2pack(o0, o1);
                }
            }
        }
        return;
    }

    // ---- EPI 0: bias store (fp32) ----
    #pragma unroll
    for (int i = 0; i < 2; i++) {
        #pragma unroll
        for (int hm = 0; hm < 2; hm++) {
            const int ml = wm * 32 + i * 16 + hm * 8 + (lane >> 2);
            if (ml >= row_cap) continue;
            float* outp = Cdst + (size_t)(row_base + ml) * 512 + cbase;
            #pragma unroll
            for (int j = 0; j < 8; j++) {
                float o0 = acc[i][j][hm * 2 + 0];
                float o1 = acc[i][j][hm * 2 + 1];
                if (beff) {
                    o0 += beff[cbase + j * 8];
                    o1 += beff[cbase + j * 8 + 1];
                }
                *(float2*)(outp + j * 8) = make_float2(o0, o1);
            }
        }
    }
}

// ======================================================================
// Head FC layer: grid (n-tiles of 64, 32 b), block 512 = 8 k-groups x 64.
// ======================================================================
template<int AGG, int RELU>
__global__ __launch_bounds__(512)
void head_fc(const float* __restrict__ X, const float* __restrict__ W,
             const float* __restrict__ bias, float* __restrict__ Y, int Nout)
{
    __shared__ float xs[512];
    __shared__ float red[8][64];

    const int b   = blockIdx.y;
    const int n0  = blockIdx.x * 64;
    const int tid = threadIdx.x;
    const int nl  = tid & 63;
    const int kg  = tid >> 6;

    if (AGG) {
        const float* p = g_PART + (size_t)(b * 5) * 512 + tid;
        xs[tid] = p[0] + p[512] + p[1024] + p[1536] + p[2048];
    } else {
        xs[tid] = X[(size_t)b * 512 + tid];
    }
    __syncthreads();

    const int n = n0 + nl;
    float acc = 0.f;
    if (n < Nout) {
        const float* wp = W + (size_t)(kg * 64) * Nout + n;
        #pragma unroll 16
        for (int kk = 0; kk < 64; kk++)
            acc = fmaf(xs[kg * 64 + kk], wp[(size_t)kk * Nout], acc);
    }
    red[kg][nl] = acc;
    __syncthreads();
    if (kg == 0 && n < Nout) {
        float v = bias[n];
        #pragma unroll
        for (int g = 0; g < 8; g++) v += red[g][nl];
        if (RELU) v = fmaxf(v, 0.f);
        Y[(size_t)b * Nout + n] = v;
    }
}

// ======================================================================
extern "C" void kernel_launch(void* const* d_in, const int* in_sizes, int n_in,
                              void* d_out, int out_size)
{
    const float* x    = (const float*)d_in[0];
    const float* g_w1 = (const float*)d_in[1];
    const float* g_b1 = (const float*)d_in[2];
    const float* g_w2 = (const float*)d_in[3];
    const float* g_b2 = (const float*)d_in[4];
    const float* g_w3 = (const float*)d_in[5];
    const float* g_b3 = (const float*)d_in[6];
    const float* f_w1 = (const float*)d_in[7];
    const float* f_b1 = (const float*)d_in[8];
    const float* f_w2 = (const float*)d_in[9];
    const float* f_b2 = (const float*)d_in[10];
    const float* f_w3 = (const float*)d_in[11];
    const float* f_b3 = (const float*)d_in[12];
    float* out = (float*)d_out;

    float *pPART, *pZ1, *pZ2;
    u32 *pW1i, *pW2i, *pW3i, *pUh, *pVh;
    cudaGetSymbolAddress((void**)&pPART, g_PART);
    cudaGetSymbolAddress((void**)&pZ1,   g_Z1);
    cudaGetSymbolAddress((void**)&pZ2,   g_Z2);
    cudaGetSymbolAddress((void**)&pW1i,  g_W1img);
    cudaGetSymbolAddress((void**)&pW2i,  g_W2img);
    cudaGetSymbolAddress((void**)&pW3i,  g_W3img);
    cudaGetSymbolAddress((void**)&pUh,   g_Uh);
    cudaGetSymbolAddress((void**)&pVh,   g_Vh);

    cudaFuncSetAttribute(gemm_tc<2,3,0>, cudaFuncAttributeMaxDynamicSharedMemorySize, SMEM_RING);
    cudaFuncSetAttribute(gemm_tc<1,2,1>, cudaFuncAttributeMaxDynamicSharedMemorySize, SMEM_RING);
    cudaFuncSetAttribute(gemm_tc<3,1,1>, cudaFuncAttributeMaxDynamicSharedMemorySize, SMEM_RING);

    // repack all g-network weights into fp16 fragment images
    repack_w<<<2048, 256>>>(g_w1, g_w1 + 512 * 512, g_w2, g_w3);

    // U | V in one launch -> fp16-packed rows (x>=4 -> W1 bottom, V out)
    gemm_tc<2,3,0><<<dim3(8, 7), 256, SMEM_RING>>>(x, pW1i, g_b1,
                                                   (float*)pUh, (float*)pVh, M_ROWS);

    // h2 = relu(relu(U_i+V_j) @ W2 + b2) -> fp16 A-fragment image
    gemm_tc<1,2,1><<<dim3(4, 160), 256, SMEM_RING>>>(nullptr, pW2i, g_b2,
                                                     nullptr, nullptr, 0);

    // h3 GEMM (A,B via cp.async images) fused with masked pair reduction
    gemm_tc<3,1,1><<<dim3(4, 160), 256, SMEM_RING>>>(nullptr, pW3i, g_b3,
                                                     pPART, nullptr, 0);

    // f head
    head_fc<1,1><<<dim3(8,  B_), 512>>>(nullptr, f_w1, f_b1, pZ1, 512);
    head_fc<0,1><<<dim3(8,  B_), 512>>>(pZ1,     f_w2, f_b2, pZ2, 512);
    head_fc<0,0><<<dim3(16, B_), 512>>>(pZ2,     f_w3, f_b3, out, C_);
}